// round 15
// baseline (speedup 1.0000x reference)
#include <cuda_runtime.h>
#include <cuda_fp16.h>
#include <cstdint>

#define B_SZ 4096
#define D_SZ 4096
#define W_SZ 4
#define H_SZ 512
#define BKH 32   // halves per k-iteration (64 B rows)

// Static scratch (allocation-free). fp16 GEMM operands stored pair-permuted:
// within each 32-half k-group (16 pairs), pair p (halves 2p,2p+1) is stored at
// pair-position pos16(p) = 4*(p&3) + (p>>2). A thread (tig) then finds pairs
// {tig, tig+4, tig+8, tig+12} contiguous -> one LDS.128 per fragment covering
// BOTH m16n8k16 k-steps of a 32-half chunk.
__device__ __half g_h[B_SZ * H_SZ];            // fp16(silu(G@w1)), [b][h_perm]
__device__ __half g_gt[B_SZ * D_SZ];           // fp16 G, [b][d_perm]
__device__ __half g_w1t[H_SZ * D_SZ];          // fp16 w1^T, [h][d_perm]
__device__ __half g_w2t[D_SZ * W_SZ * H_SZ];   // fp16 w2^T, [n][h_perm]
__device__ float  g_p[2 * B_SZ * H_SZ];        // gemm1 split-K partials (fp32)
__device__ unsigned g_cnt[32 * 8];             // split-K completion counters

// ---------------------------------------------------------------------------
// helpers
// ---------------------------------------------------------------------------
__device__ __forceinline__ void mma_f16(float d[4], const uint32_t a[4], const uint32_t b[2]) {
    asm volatile(
        "mma.sync.aligned.m16n8k16.row.col.f32.f16.f16.f32 "
        "{%0,%1,%2,%3}, {%4,%5,%6,%7}, {%8,%9}, {%0,%1,%2,%3};\n"
        : "+f"(d[0]), "+f"(d[1]), "+f"(d[2]), "+f"(d[3])
        : "r"(a[0]), "r"(a[1]), "r"(a[2]), "r"(a[3]), "r"(b[0]), "r"(b[1]));
}

__device__ __forceinline__ float silu(float v) {
    return v * (1.0f / (1.0f + __expf(-v)));
}

__device__ __forceinline__ uint32_t smem_u32(const void* p) {
    uint32_t a;
    asm("{ .reg .u64 t; cvta.to.shared.u64 t, %1; cvt.u32.u64 %0, t; }" : "=r"(a) : "l"(p));
    return a;
}

__device__ __forceinline__ void cp16u(uint32_t dst_smem, const void* src) {
    asm volatile("cp.async.cg.shared.global [%0], [%1], 16;\n"
                 :: "r"(dst_smem), "l"(src) : "memory");
}
__device__ __forceinline__ void cp_commit() {
    asm volatile("cp.async.commit_group;\n" ::: "memory");
}
template <int N>
__device__ __forceinline__ void cp_wait() {
    asm volatile("cp.async.wait_group %0;\n" :: "n"(N) : "memory");
}

__device__ __forceinline__ uint4 lds128(uint32_t addr) {
    uint4 v;
    asm volatile("ld.shared.v4.b32 {%0,%1,%2,%3}, [%4];"
                 : "=r"(v.x), "=r"(v.y), "=r"(v.z), "=r"(v.w) : "r"(addr));
    return v;
}

// streaming (evict-first) global accessors — keep w2t/h resident in L2
__device__ __forceinline__ float4 ldg_cs4(const float4* p) {
    float4 v;
    asm volatile("ld.global.cs.v4.f32 {%0,%1,%2,%3}, [%4];"
                 : "=f"(v.x), "=f"(v.y), "=f"(v.z), "=f"(v.w) : "l"(p));
    return v;
}
__device__ __forceinline__ float ldg_cs(const float* p) {
    float v;
    asm volatile("ld.global.cs.f32 %0, [%1];" : "=f"(v) : "l"(p));
    return v;
}
__device__ __forceinline__ void stg_cs4(float4* p, float4 v) {
    asm volatile("st.global.cs.v4.f32 [%0], {%1,%2,%3,%4};"
                 :: "l"(p), "f"(v.x), "f"(v.y), "f"(v.z), "f"(v.w));
}
__device__ __forceinline__ void stg_cs(float* p, float v) {
    asm volatile("st.global.cs.f32 [%0], %1;" :: "l"(p), "f"(v));
}

// 32-half tile rows are 64 B; 16 B chunk q stored at q ^ (row & 3).
__device__ __forceinline__ uint32_t frag_addr(uint32_t base, int row, int tig) {
    return base + (uint32_t)row * 64u + (uint32_t)((tig ^ (row & 3)) << 4);
}

__host__ __device__ __forceinline__ int pos16(int p) {
    return ((p & 3) << 2) | (p >> 2);
}

// ---------------------------------------------------------------------------
// Prepass 1 (merged, coalesced): blocks [0, NG_G) do G fp32->fp16 pair-permute
// (one 16B output chunk per thread); blocks [NG_G, +NB_W1T) transpose w1.
// ---------------------------------------------------------------------------
#define NG_G   (B_SZ * D_SZ / 8 / 256)           // 8192 blocks
#define NB_W1T ((H_SZ / 32) * (D_SZ / 32))       // 2048 blocks

__global__ __launch_bounds__(256) void prepass1(const float* __restrict__ gi,
                                                const float* __restrict__ w1) {
    __shared__ float t[32][33];
    int bid = blockIdx.x, tid = threadIdx.x;

    if (bid < NG_G) {
        int tt = bid * 256 + tid;                // chunk id
        int g = tt >> 2, q = tt & 3;             // group, chunk-in-group
        const float2* s = reinterpret_cast<const float2*>(gi) + (size_t)g * 16 + q;
        uint32_t pk[4];
#pragma unroll
        for (int i = 0; i < 4; i++) {            // slot 4q+i <- original pair 4i+q
            float2 v = s[4 * i];
            __half2 h = __floats2half2_rn(v.x, v.y);
            pk[i] = *reinterpret_cast<uint32_t*>(&h);
        }
        reinterpret_cast<uint4*>(g_gt)[tt] = make_uint4(pk[0], pk[1], pk[2], pk[3]);
    } else {
        int idx = bid - NG_G;
        int bx = idx & 15, by = idx >> 4;
        int c0 = bx * 32, r0 = by * 32;
        int tx = tid & 31, ty = tid >> 5;
#pragma unroll
        for (int j = ty; j < 32; j += 8)
            t[j][tx] = w1[(size_t)(r0 + j) * H_SZ + c0 + tx];
        __syncthreads();
        int px = 2 * pos16(tx >> 1) + (tx & 1);
#pragma unroll
        for (int j = ty; j < 32; j += 8)
            g_w1t[(size_t)(c0 + j) * D_SZ + r0 + px] = __float2half_rn(t[tx][j]);
    }
}

// ===========================================================================
// Kernel 1: split-K partial of G@w1 (z<2) with FUSED reduce (last twin of a
// (bm,bn) tile computes h = fp16(silu(p0+p1)), pair-permuted) + w2->w2^T
// transpose slice (z==2). GEMM: BM=128 BN=64, BK=32 halves, S=4 (48 KB),
// warp grid 4x2, 32x32, 3 CTAs/SM.
// ===========================================================================
#define S1 4
#define A_STG 8192                        // 128 rows * 64 B
#define B_STG 4096                        // 64 rows * 64 B
#define G1SMEM (S1 * (A_STG + B_STG))     // 49152 B

extern __shared__ float dynsmem[];

__global__ __launch_bounds__(256, 3) void dsc_gemm1(const __half* __restrict__ G,
                                                    const __half* __restrict__ w1t,
                                                    const float* __restrict__ w2) {
    int tid = threadIdx.x;

    if (blockIdx.z == 2) {
        // --- w2 [H][D*W] -> w2t [D*W][H], permute along H. 256 blocks x 32 tiles.
        float* t = dynsmem;                              // [32][33]
        int tx = tid & 31, ty = tid >> 5;
        int bid = blockIdx.y * 32 + blockIdx.x;          // 0..255
        int px = 2 * pos16(tx >> 1) + (tx & 1);
#pragma unroll 1
        for (int tt = 0; tt < 32; tt++) {
            int tile = bid * 32 + tt;
            int cx = tile & 511, cy = tile >> 9;
            int c0 = cx * 32, r0 = cy * 32;
#pragma unroll
            for (int j = ty; j < 32; j += 8)
                t[j * 33 + tx] = w2[(size_t)(r0 + j) * (D_SZ * W_SZ) + c0 + tx];
            __syncthreads();
#pragma unroll
            for (int j = ty; j < 32; j += 8)
                g_w2t[(size_t)(c0 + j) * H_SZ + r0 + px] = __float2half_rn(t[tx * 33 + j]);
            __syncthreads();
        }
        return;
    }

    uint32_t sb = smem_u32(dynsmem);
    uint32_t aS = sb, bS = sb + S1 * A_STG;

    int lane = tid & 31, warp = tid >> 5;
    int warpM = warp >> 1, warpN = warp & 1;
    int g = lane >> 2, tig = lane & 3;
    int bm = blockIdx.x, bn = blockIdx.y, sk = blockIdx.z;

    const __half* A = G + (size_t)bm * 128 * D_SZ + sk * 2048;
    const __half* B = w1t + (size_t)bn * 64 * D_SZ + sk * 2048;

    auto load_stage = [&](int j) {
        uint32_t a_s = aS + (j & (S1 - 1)) * A_STG;
        uint32_t b_s = bS + (j & (S1 - 1)) * B_STG;
#pragma unroll
        for (int t = 0; t < 2; t++) {
            int id = tid + 256 * t;
            int r = id >> 2, q = id & 3;
            cp16u(a_s + r * 64 + ((q ^ (r & 3)) << 4), A + (size_t)r * D_SZ + j * BKH + q * 8);
        }
        {
            int r = tid >> 2, q = tid & 3;
            cp16u(b_s + r * 64 + ((q ^ (r & 3)) << 4), B + (size_t)r * D_SZ + j * BKH + q * 8);
        }
    };

    const int nIter = 2048 / BKH;  // 64
#pragma unroll
    for (int s = 0; s < S1 - 1; s++) { load_stage(s); cp_commit(); }

    float acc[2][4][4] = {};
    for (int it = 0; it < nIter; it++) {
        cp_wait<S1 - 2>();
        __syncthreads();
        int nxt = it + S1 - 1;
        if (nxt < nIter) load_stage(nxt);
        cp_commit();
        uint32_t a_s = aS + (it & (S1 - 1)) * A_STG;
        uint32_t b_s = bS + (it & (S1 - 1)) * B_STG;

        uint4 bb[4], alo[2], ahi[2];
#pragma unroll
        for (int nt = 0; nt < 4; nt++)
            bb[nt] = lds128(frag_addr(b_s, warpN * 32 + nt * 8 + g, tig));
#pragma unroll
        for (int mt = 0; mt < 2; mt++) {
            int r = warpM * 32 + mt * 16 + g;
            alo[mt] = lds128(frag_addr(a_s, r, tig));
            ahi[mt] = lds128(frag_addr(a_s, r + 8, tig));
        }
#pragma unroll
        for (int ks = 0; ks < 2; ks++) {
#pragma unroll
            for (int mt = 0; mt < 2; mt++) {
                uint32_t a[4];
                if (ks == 0) { a[0] = alo[mt].x; a[1] = ahi[mt].x; a[2] = alo[mt].y; a[3] = ahi[mt].y; }
                else         { a[0] = alo[mt].z; a[1] = ahi[mt].z; a[2] = alo[mt].w; a[3] = ahi[mt].w; }
#pragma unroll
                for (int nt = 0; nt < 4; nt++) {
                    uint32_t b[2];
                    if (ks == 0) { b[0] = bb[nt].x; b[1] = bb[nt].y; }
                    else         { b[0] = bb[nt].z; b[1] = bb[nt].w; }
                    mma_f16(acc[mt][nt], a, b);
                }
            }
        }
    }

    // raw fp32 partial store (natural layout, plain stores -> L2-resident)
    float* P = g_p + (size_t)sk * B_SZ * H_SZ;
#pragma unroll
    for (int mt = 0; mt < 2; mt++) {
#pragma unroll
        for (int nt = 0; nt < 4; nt++) {
            int row = bm * 128 + warpM * 32 + mt * 16 + g;
            int col = bn * 64 + warpN * 32 + nt * 8 + 2 * tig;
            *reinterpret_cast<float2*>(P + (size_t)row * H_SZ + col) =
                make_float2(acc[mt][nt][0], acc[mt][nt][1]);
            *reinterpret_cast<float2*>(P + (size_t)(row + 8) * H_SZ + col) =
                make_float2(acc[mt][nt][2], acc[mt][nt][3]);
        }
    }

    // Fused split-K reduce: the LAST twin of this (bm,bn) tile produces h.
    __threadfence();
    __shared__ unsigned s_old;
    if (tid == 0) s_old = atomicAdd(&g_cnt[bm * 8 + bn], 1u);
    __syncthreads();
    if (s_old == 1u) {
        if (tid == 0) g_cnt[bm * 8 + bn] = 0u;   // reset for next graph replay
        __threadfence();                         // acquire partner's partial
        const float2* P0 = reinterpret_cast<const float2*>(g_p);
        const float2* P1 = P0 + (size_t)(B_SZ * H_SZ / 2);
#pragma unroll
        for (int c4 = 0; c4 < 4; c4++) {
            int c = c4 * 256 + tid;              // 1024 chunks: 128 rows x 8
            int row_l = c >> 3, qq = c & 7;
            int row = bm * 128 + row_l;
            int g2 = qq >> 2, q = qq & 3;
            size_t base = (size_t)row * (H_SZ / 2) + bn * 32 + g2 * 16;
            uint32_t pk[4];
#pragma unroll
            for (int i = 0; i < 4; i++) {        // slot 4q+i <- natural pair 4i+q
                float2 a = P0[base + 4 * i + q];
                float2 b = P1[base + 4 * i + q];
                __half2 hh = __floats2half2_rn(silu(a.x + b.x), silu(a.y + b.y));
                pk[i] = *reinterpret_cast<uint32_t*>(&hh);
            }
            reinterpret_cast<uint4*>(g_h)[(size_t)row * (H_SZ / 8) + bn * 8 + qq] =
                make_uint4(pk[0], pk[1], pk[2], pk[3]);
        }
    }
}

// ===========================================================================
// Kernel 2 (unchanged, at the HMMA cap): kernels = h@w2^T + b2, fused conv.
// M=4096 N=16384 K=512. BM=128 BN=64, warp grid 4x2, 32x32,
// S=5 stages (60 KB), 3 CTAs/SM, streaming epilogue.
// ===========================================================================
#define S2 5
#define G2SMEM (S2 * (A_STG + B_STG))     // 61440 B
#define SC_STRIDE 68

__global__ __launch_bounds__(256, 3) void dsc_gemm2(const float* __restrict__ x,
                                                    const float* __restrict__ cache,
                                                    const __half* __restrict__ w2t,
                                                    const float* __restrict__ b2,
                                                    float* __restrict__ out,
                                                    float* __restrict__ new_cache) {
    uint32_t sb = smem_u32(dynsmem);
    uint32_t aS = sb, bS = sb + S2 * A_STG;

    int tid = threadIdx.x, lane = tid & 31, warp = tid >> 5;
    int warpM = warp >> 1, warpN = warp & 1;
    int g = lane >> 2, tig = lane & 3;
    int bm = blockIdx.x, bn = blockIdx.y;

    const __half* A = g_h + (size_t)bm * 128 * H_SZ;
    const __half* B = w2t + (size_t)bn * 64 * H_SZ;

    auto load_stage = [&](int j) {
        uint32_t a_s = aS + (j % S2) * A_STG;
        uint32_t b_s = bS + (j % S2) * B_STG;
#pragma unroll
        for (int t = 0; t < 2; t++) {
            int id = tid + 256 * t;
            int r = id >> 2, q = id & 3;
            cp16u(a_s + r * 64 + ((q ^ (r & 3)) << 4), A + (size_t)r * H_SZ + j * BKH + q * 8);
        }
        {
            int r = tid >> 2, q = tid & 3;
            cp16u(b_s + r * 64 + ((q ^ (r & 3)) << 4), B + (size_t)r * H_SZ + j * BKH + q * 8);
        }
    };

    const int nIter = H_SZ / BKH;  // 16
#pragma unroll
    for (int s = 0; s < S2 - 1; s++) { load_stage(s); cp_commit(); }

    float acc[2][4][4] = {};
    for (int it = 0; it < nIter; it++) {
        cp_wait<S2 - 2>();
        __syncthreads();
        int nxt = it + S2 - 1;
        if (nxt < nIter) load_stage(nxt);
        cp_commit();
        uint32_t a_s = aS + (it % S2) * A_STG;
        uint32_t b_s = bS + (it % S2) * B_STG;

        uint4 bb[4], alo[2], ahi[2];
#pragma unroll
        for (int nt = 0; nt < 4; nt++)
            bb[nt] = lds128(frag_addr(b_s, warpN * 32 + nt * 8 + g, tig));
#pragma unroll
        for (int mt = 0; mt < 2; mt++) {
            int r = warpM * 32 + mt * 16 + g;
            alo[mt] = lds128(frag_addr(a_s, r, tig));
            ahi[mt] = lds128(frag_addr(a_s, r + 8, tig));
        }
#pragma unroll
        for (int ks = 0; ks < 2; ks++) {
#pragma unroll
            for (int mt = 0; mt < 2; mt++) {
                uint32_t a[4];
                if (ks == 0) { a[0] = alo[mt].x; a[1] = ahi[mt].x; a[2] = alo[mt].y; a[3] = ahi[mt].y; }
                else         { a[0] = alo[mt].z; a[1] = ahi[mt].z; a[2] = alo[mt].w; a[3] = ahi[mt].w; }
#pragma unroll
                for (int nt = 0; nt < 4; nt++) {
                    uint32_t b[2];
                    if (ks == 0) { b[0] = bb[nt].x; b[1] = bb[nt].y; }
                    else         { b[0] = bb[nt].z; b[1] = bb[nt].w; }
                    mma_f16(acc[mt][nt], a, b);
                }
            }
        }
    }

    __syncthreads();  // mainloop smem reads done; reuse as C tile

    // Single-pass epilogue: all 8 warps dump their 32x32 quadrant, then conv.
    float* sC = dynsmem;
#pragma unroll
    for (int mt = 0; mt < 2; mt++) {
#pragma unroll
        for (int nt = 0; nt < 4; nt++) {
            int r = warpM * 32 + mt * 16 + g;
            int c = warpN * 32 + nt * 8 + 2 * tig;
            sC[r * SC_STRIDE + c] = acc[mt][nt][0];
            sC[r * SC_STRIDE + c + 1] = acc[mt][nt][1];
            sC[(r + 8) * SC_STRIDE + c] = acc[mt][nt][2];
            sC[(r + 8) * SC_STRIDE + c + 1] = acc[mt][nt][3];
        }
    }
    __syncthreads();

    const float4* cache4 = reinterpret_cast<const float4*>(cache);
    float4* ncache4 = reinterpret_cast<float4*>(new_cache);
    const float4* b2_4 = reinterpret_cast<const float4*>(b2);

    int d_local = tid & 15;
    int d = bn * 16 + d_local;
    float4 bias = b2_4[d];
#pragma unroll
    for (int i = 0; i < 8; i++) {
        int b_local = (tid >> 4) + i * 16;
        int b = bm * 128 + b_local;
        size_t bd = (size_t)b * D_SZ + d;

        float4 kv = *reinterpret_cast<const float4*>(sC + b_local * SC_STRIDE + d_local * 4);
        kv.x += bias.x; kv.y += bias.y; kv.z += bias.z; kv.w += bias.w;

        float4 c4 = ldg_cs4(cache4 + bd);
        float xv = ldg_cs(x + bd);

        float nc0 = c4.y, nc1 = c4.z, nc2 = c4.w, nc3 = xv;
        float s = nc0 * kv.x + nc1 * kv.y + nc2 * kv.z + nc3 * kv.w;

        stg_cs(out + bd, silu(s));
        stg_cs4(ncache4 + bd, make_float4(nc0, nc1, nc2, nc3));
    }
}

// ---------------------------------------------------------------------------
// launch
// ---------------------------------------------------------------------------
extern "C" void kernel_launch(void* const* d_in, const int* in_sizes, int n_in,
                              void* d_out, int out_size) {
    const float* x     = (const float*)d_in[0];  // (B,1,D)
    const float* gi    = (const float*)d_in[1];  // (B,1,D)
    const float* cache = (const float*)d_in[2];  // (B,D,W)
    const float* w1    = (const float*)d_in[3];  // (D,H)
    const float* w2    = (const float*)d_in[4];  // (H,D*W)
    const float* b2    = (const float*)d_in[5];  // (D*W)

    float* out    = (float*)d_out;               // (B,1,D)
    float* ncache = out + (size_t)B_SZ * D_SZ;   // (B,D,W)

    cudaFuncSetAttribute(dsc_gemm1, cudaFuncAttributeMaxDynamicSharedMemorySize, G1SMEM);
    cudaFuncSetAttribute(dsc_gemm2, cudaFuncAttributeMaxDynamicSharedMemorySize, G2SMEM);

    __half* gt;  cudaGetSymbolAddress((void**)&gt,  g_gt);
    __half* w1t; cudaGetSymbolAddress((void**)&w1t, g_w1t);
    __half* w2t; cudaGetSymbolAddress((void**)&w2t, g_w2t);

    // P1: G permute (coalesced) and w1 transpose run concurrently
    prepass1<<<NG_G + NB_W1T, 256>>>(gi, w1);

    // gemm1 (z<2: split-K compute + fused reduce) + w2 transpose (z==2)
    dsc_gemm1<<<dim3(32, 8, 3), 256, G1SMEM>>>(gt, w1t, w2);

    dsc_gemm2<<<dim3(32, 256), 256, G2SMEM>>>(x, cache, w2t, b2, out, ncache);
}

// round 16
// speedup vs baseline: 1.0496x; 1.0496x over previous
#include <cuda_runtime.h>
#include <cuda_fp16.h>
#include <cstdint>

#define B_SZ 4096
#define D_SZ 4096
#define W_SZ 4
#define H_SZ 512
#define BKH 32   // halves per k-iteration (64 B rows)

// Static scratch (allocation-free). fp16 GEMM operands stored pair-permuted:
// within each 32-half k-group (16 pairs), pair p (halves 2p,2p+1) is stored at
// pair-position pos16(p) = 4*(p&3) + (p>>2). A thread (tig) then finds pairs
// {tig, tig+4, tig+8, tig+12} contiguous -> one LDS.128 per fragment covering
// BOTH m16n8k16 k-steps of a 32-half chunk.
__device__ __half g_h[B_SZ * H_SZ];            // fp16(silu(G@w1)), [b][h_perm]
__device__ __half g_gt[B_SZ * D_SZ];           // fp16 G, [b][d_perm]
__device__ __half g_w1t[H_SZ * D_SZ];          // fp16 w1^T, [h][d_perm]
__device__ __half g_w2t[D_SZ * W_SZ * H_SZ];   // fp16 w2^T, [n][h_perm]

// ---------------------------------------------------------------------------
// helpers
// ---------------------------------------------------------------------------
__device__ __forceinline__ void mma_f16(float d[4], const uint32_t a[4], const uint32_t b[2]) {
    asm volatile(
        "mma.sync.aligned.m16n8k16.row.col.f32.f16.f16.f32 "
        "{%0,%1,%2,%3}, {%4,%5,%6,%7}, {%8,%9}, {%0,%1,%2,%3};\n"
        : "+f"(d[0]), "+f"(d[1]), "+f"(d[2]), "+f"(d[3])
        : "r"(a[0]), "r"(a[1]), "r"(a[2]), "r"(a[3]), "r"(b[0]), "r"(b[1]));
}

__device__ __forceinline__ float silu(float v) {
    return v * (1.0f / (1.0f + __expf(-v)));
}

__device__ __forceinline__ uint32_t smem_u32(const void* p) {
    uint32_t a;
    asm("{ .reg .u64 t; cvta.to.shared.u64 t, %1; cvt.u32.u64 %0, t; }" : "=r"(a) : "l"(p));
    return a;
}

__device__ __forceinline__ void cp16u(uint32_t dst_smem, const void* src) {
    asm volatile("cp.async.cg.shared.global [%0], [%1], 16;\n"
                 :: "r"(dst_smem), "l"(src) : "memory");
}
__device__ __forceinline__ void cp_commit() {
    asm volatile("cp.async.commit_group;\n" ::: "memory");
}
template <int N>
__device__ __forceinline__ void cp_wait() {
    asm volatile("cp.async.wait_group %0;\n" :: "n"(N) : "memory");
}

__device__ __forceinline__ uint4 lds128(uint32_t addr) {
    uint4 v;
    asm volatile("ld.shared.v4.b32 {%0,%1,%2,%3}, [%4];"
                 : "=r"(v.x), "=r"(v.y), "=r"(v.z), "=r"(v.w) : "r"(addr));
    return v;
}

// streaming (evict-first) global accessors — keep w2t/h resident in L2
__device__ __forceinline__ float4 ldg_cs4(const float4* p) {
    float4 v;
    asm volatile("ld.global.cs.v4.f32 {%0,%1,%2,%3}, [%4];"
                 : "=f"(v.x), "=f"(v.y), "=f"(v.z), "=f"(v.w) : "l"(p));
    return v;
}
__device__ __forceinline__ float ldg_cs(const float* p) {
    float v;
    asm volatile("ld.global.cs.f32 %0, [%1];" : "=f"(v) : "l"(p));
    return v;
}
__device__ __forceinline__ void stg_cs4(float4* p, float4 v) {
    asm volatile("st.global.cs.v4.f32 [%0], {%1,%2,%3,%4};"
                 :: "l"(p), "f"(v.x), "f"(v.y), "f"(v.z), "f"(v.w));
}
__device__ __forceinline__ void stg_cs(float* p, float v) {
    asm volatile("st.global.cs.f32 [%0], %1;" :: "l"(p), "f"(v));
}

// 32-half tile rows are 64 B; 16 B chunk q stored at q ^ (row & 3).
__device__ __forceinline__ uint32_t frag_addr(uint32_t base, int row, int tig) {
    return base + (uint32_t)row * 64u + (uint32_t)((tig ^ (row & 3)) << 4);
}

__host__ __device__ __forceinline__ int pos16(int p) {
    return ((p & 3) << 2) | (p >> 2);
}

// ---------------------------------------------------------------------------
// Prepass 1 (merged, coalesced): blocks [0, NG_G) do G fp32->fp16 pair-permute
// (one 16B output chunk per thread); blocks [NG_G, +NB_W1T) transpose w1.
// ---------------------------------------------------------------------------
#define NG_G   (B_SZ * D_SZ / 8 / 256)           // 8192 blocks
#define NB_W1T ((H_SZ / 32) * (D_SZ / 32))       // 2048 blocks

__global__ __launch_bounds__(256) void prepass1(const float* __restrict__ gi,
                                                const float* __restrict__ w1) {
    __shared__ float t[32][33];
    int bid = blockIdx.x, tid = threadIdx.x;

    if (bid < NG_G) {
        int tt = bid * 256 + tid;                // chunk id
        int g = tt >> 2, q = tt & 3;             // group, chunk-in-group
        const float2* s = reinterpret_cast<const float2*>(gi) + (size_t)g * 16 + q;
        uint32_t pk[4];
#pragma unroll
        for (int i = 0; i < 4; i++) {            // slot 4q+i <- original pair 4i+q
            float2 v = s[4 * i];
            __half2 h = __floats2half2_rn(v.x, v.y);
            pk[i] = *reinterpret_cast<uint32_t*>(&h);
        }
        reinterpret_cast<uint4*>(g_gt)[tt] = make_uint4(pk[0], pk[1], pk[2], pk[3]);
    } else {
        int idx = bid - NG_G;
        int bx = idx & 15, by = idx >> 4;
        int c0 = bx * 32, r0 = by * 32;
        int tx = tid & 31, ty = tid >> 5;
#pragma unroll
        for (int j = ty; j < 32; j += 8)
            t[j][tx] = w1[(size_t)(r0 + j) * H_SZ + c0 + tx];
        __syncthreads();
        int px = 2 * pos16(tx >> 1) + (tx & 1);
#pragma unroll
        for (int j = ty; j < 32; j += 8)
            g_w1t[(size_t)(c0 + j) * D_SZ + r0 + px] = __float2half_rn(t[tx][j]);
    }
}

// ===========================================================================
// Kernel 1: h = fp16(silu(G @ w1)) written DIRECTLY (no split-K, no reduce),
// plus w2->w2^T transpose slice (z==1).
// GEMM: BM=128 BN=64, BK=32 halves, K=4096 (128 iters), S=4 (48 KB),
// warp grid 4x2, 32x32, 3 CTAs/SM. Critical SMs hold 2 CTAs (16 warps) —
// the proven at-cap residency; span matches split-K by the fixed-rate model.
// ===========================================================================
#define S1 4
#define A_STG 8192                        // 128 rows * 64 B
#define B_STG 4096                        // 64 rows * 64 B
#define G1SMEM (S1 * (A_STG + B_STG))     // 49152 B

extern __shared__ float dynsmem[];

__global__ __launch_bounds__(256, 3) void dsc_gemm1(const __half* __restrict__ G,
                                                    const __half* __restrict__ w1t,
                                                    const float* __restrict__ w2) {
    int tid = threadIdx.x;

    if (blockIdx.z == 1) {
        // --- w2 [H][D*W] -> w2t [D*W][H], permute along H. 256 blocks x 32 tiles.
        float* t = dynsmem;                              // [32][33]
        int tx = tid & 31, ty = tid >> 5;
        int bid = blockIdx.y * 32 + blockIdx.x;          // 0..255
        int px = 2 * pos16(tx >> 1) + (tx & 1);
#pragma unroll 1
        for (int tt = 0; tt < 32; tt++) {
            int tile = bid * 32 + tt;
            int cx = tile & 511, cy = tile >> 9;
            int c0 = cx * 32, r0 = cy * 32;
#pragma unroll
            for (int j = ty; j < 32; j += 8)
                t[j * 33 + tx] = w2[(size_t)(r0 + j) * (D_SZ * W_SZ) + c0 + tx];
            __syncthreads();
#pragma unroll
            for (int j = ty; j < 32; j += 8)
                g_w2t[(size_t)(c0 + j) * H_SZ + r0 + px] = __float2half_rn(t[tx * 33 + j]);
            __syncthreads();
        }
        return;
    }

    uint32_t sb = smem_u32(dynsmem);
    uint32_t aS = sb, bS = sb + S1 * A_STG;

    int lane = tid & 31, warp = tid >> 5;
    int warpM = warp >> 1, warpN = warp & 1;
    int g = lane >> 2, tig = lane & 3;
    int bm = blockIdx.x, bn = blockIdx.y;

    const __half* A = G + (size_t)bm * 128 * D_SZ;
    const __half* B = w1t + (size_t)bn * 64 * D_SZ;

    auto load_stage = [&](int j) {
        uint32_t a_s = aS + (j & (S1 - 1)) * A_STG;
        uint32_t b_s = bS + (j & (S1 - 1)) * B_STG;
#pragma unroll
        for (int t = 0; t < 2; t++) {
            int id = tid + 256 * t;
            int r = id >> 2, q = id & 3;
            cp16u(a_s + r * 64 + ((q ^ (r & 3)) << 4), A + (size_t)r * D_SZ + j * BKH + q * 8);
        }
        {
            int r = tid >> 2, q = tid & 3;
            cp16u(b_s + r * 64 + ((q ^ (r & 3)) << 4), B + (size_t)r * D_SZ + j * BKH + q * 8);
        }
    };

    const int nIter = D_SZ / BKH;  // 128
#pragma unroll
    for (int s = 0; s < S1 - 1; s++) { load_stage(s); cp_commit(); }

    float acc[2][4][4] = {};
    for (int it = 0; it < nIter; it++) {
        cp_wait<S1 - 2>();
        __syncthreads();
        int nxt = it + S1 - 1;
        if (nxt < nIter) load_stage(nxt);
        cp_commit();
        uint32_t a_s = aS + (it & (S1 - 1)) * A_STG;
        uint32_t b_s = bS + (it & (S1 - 1)) * B_STG;

        uint4 bb[4], alo[2], ahi[2];
#pragma unroll
        for (int nt = 0; nt < 4; nt++)
            bb[nt] = lds128(frag_addr(b_s, warpN * 32 + nt * 8 + g, tig));
#pragma unroll
        for (int mt = 0; mt < 2; mt++) {
            int r = warpM * 32 + mt * 16 + g;
            alo[mt] = lds128(frag_addr(a_s, r, tig));
            ahi[mt] = lds128(frag_addr(a_s, r + 8, tig));
        }
#pragma unroll
        for (int ks = 0; ks < 2; ks++) {
#pragma unroll
            for (int mt = 0; mt < 2; mt++) {
                uint32_t a[4];
                if (ks == 0) { a[0] = alo[mt].x; a[1] = ahi[mt].x; a[2] = alo[mt].y; a[3] = ahi[mt].y; }
                else         { a[0] = alo[mt].z; a[1] = ahi[mt].z; a[2] = alo[mt].w; a[3] = ahi[mt].w; }
#pragma unroll
                for (int nt = 0; nt < 4; nt++) {
                    uint32_t b[2];
                    if (ks == 0) { b[0] = bb[nt].x; b[1] = bb[nt].y; }
                    else         { b[0] = bb[nt].z; b[1] = bb[nt].w; }
                    mma_f16(acc[mt][nt], a, b);
                }
            }
        }
    }

    // Direct h epilogue: h = fp16(silu(acc)), pair-permuted columns.
    // Each acc[mt][nt] pair {c0, c0+1} is natural pair p = c0>>1; it lands at
    // storage halves group*32 + 2*pos16(p&15) (+1). One 4B store per pair.
#pragma unroll
    for (int mt = 0; mt < 2; mt++) {
#pragma unroll
        for (int nt = 0; nt < 4; nt++) {
            int row = bm * 128 + warpM * 32 + mt * 16 + g;
            int c0 = bn * 64 + warpN * 32 + nt * 8 + 2 * tig;
            int p = c0 >> 1;
            int dest = (p & ~15) * 2 + 2 * pos16(p & 15);
            __half2 h0 = __floats2half2_rn(silu(acc[mt][nt][0]), silu(acc[mt][nt][1]));
            __half2 h1 = __floats2half2_rn(silu(acc[mt][nt][2]), silu(acc[mt][nt][3]));
            *reinterpret_cast<__half2*>(g_h + (size_t)row * H_SZ + dest) = h0;
            *reinterpret_cast<__half2*>(g_h + (size_t)(row + 8) * H_SZ + dest) = h1;
        }
    }
}

// ===========================================================================
// Kernel 2 (unchanged, at the HMMA cap): kernels = h@w2^T + b2, fused conv.
// M=4096 N=16384 K=512. BM=128 BN=64, warp grid 4x2, 32x32,
// S=5 stages (60 KB), 3 CTAs/SM, streaming epilogue.
// ===========================================================================
#define S2 5
#define G2SMEM (S2 * (A_STG + B_STG))     // 61440 B
#define SC_STRIDE 68

__global__ __launch_bounds__(256, 3) void dsc_gemm2(const float* __restrict__ x,
                                                    const float* __restrict__ cache,
                                                    const __half* __restrict__ w2t,
                                                    const float* __restrict__ b2,
                                                    float* __restrict__ out,
                                                    float* __restrict__ new_cache) {
    uint32_t sb = smem_u32(dynsmem);
    uint32_t aS = sb, bS = sb + S2 * A_STG;

    int tid = threadIdx.x, lane = tid & 31, warp = tid >> 5;
    int warpM = warp >> 1, warpN = warp & 1;
    int g = lane >> 2, tig = lane & 3;
    int bm = blockIdx.x, bn = blockIdx.y;

    const __half* A = g_h + (size_t)bm * 128 * H_SZ;
    const __half* B = w2t + (size_t)bn * 64 * H_SZ;

    auto load_stage = [&](int j) {
        uint32_t a_s = aS + (j % S2) * A_STG;
        uint32_t b_s = bS + (j % S2) * B_STG;
#pragma unroll
        for (int t = 0; t < 2; t++) {
            int id = tid + 256 * t;
            int r = id >> 2, q = id & 3;
            cp16u(a_s + r * 64 + ((q ^ (r & 3)) << 4), A + (size_t)r * H_SZ + j * BKH + q * 8);
        }
        {
            int r = tid >> 2, q = tid & 3;
            cp16u(b_s + r * 64 + ((q ^ (r & 3)) << 4), B + (size_t)r * H_SZ + j * BKH + q * 8);
        }
    };

    const int nIter = H_SZ / BKH;  // 16
#pragma unroll
    for (int s = 0; s < S2 - 1; s++) { load_stage(s); cp_commit(); }

    float acc[2][4][4] = {};
    for (int it = 0; it < nIter; it++) {
        cp_wait<S2 - 2>();
        __syncthreads();
        int nxt = it + S2 - 1;
        if (nxt < nIter) load_stage(nxt);
        cp_commit();
        uint32_t a_s = aS + (it % S2) * A_STG;
        uint32_t b_s = bS + (it % S2) * B_STG;

        uint4 bb[4], alo[2], ahi[2];
#pragma unroll
        for (int nt = 0; nt < 4; nt++)
            bb[nt] = lds128(frag_addr(b_s, warpN * 32 + nt * 8 + g, tig));
#pragma unroll
        for (int mt = 0; mt < 2; mt++) {
            int r = warpM * 32 + mt * 16 + g;
            alo[mt] = lds128(frag_addr(a_s, r, tig));
            ahi[mt] = lds128(frag_addr(a_s, r + 8, tig));
        }
#pragma unroll
        for (int ks = 0; ks < 2; ks++) {
#pragma unroll
            for (int mt = 0; mt < 2; mt++) {
                uint32_t a[4];
                if (ks == 0) { a[0] = alo[mt].x; a[1] = ahi[mt].x; a[2] = alo[mt].y; a[3] = ahi[mt].y; }
                else         { a[0] = alo[mt].z; a[1] = ahi[mt].z; a[2] = alo[mt].w; a[3] = ahi[mt].w; }
#pragma unroll
                for (int nt = 0; nt < 4; nt++) {
                    uint32_t b[2];
                    if (ks == 0) { b[0] = bb[nt].x; b[1] = bb[nt].y; }
                    else         { b[0] = bb[nt].z; b[1] = bb[nt].w; }
                    mma_f16(acc[mt][nt], a, b);
                }
            }
        }
    }

    __syncthreads();  // mainloop smem reads done; reuse as C tile

    // Single-pass epilogue: all 8 warps dump their 32x32 quadrant, then conv.
    float* sC = dynsmem;
#pragma unroll
    for (int mt = 0; mt < 2; mt++) {
#pragma unroll
        for (int nt = 0; nt < 4; nt++) {
            int r = warpM * 32 + mt * 16 + g;
            int c = warpN * 32 + nt * 8 + 2 * tig;
            sC[r * SC_STRIDE + c] = acc[mt][nt][0];
            sC[r * SC_STRIDE + c + 1] = acc[mt][nt][1];
            sC[(r + 8) * SC_STRIDE + c] = acc[mt][nt][2];
            sC[(r + 8) * SC_STRIDE + c + 1] = acc[mt][nt][3];
        }
    }
    __syncthreads();

    const float4* cache4 = reinterpret_cast<const float4*>(cache);
    float4* ncache4 = reinterpret_cast<float4*>(new_cache);
    const float4* b2_4 = reinterpret_cast<const float4*>(b2);

    int d_local = tid & 15;
    int d = bn * 16 + d_local;
    float4 bias = b2_4[d];
#pragma unroll
    for (int i = 0; i < 8; i++) {
        int b_local = (tid >> 4) + i * 16;
        int b = bm * 128 + b_local;
        size_t bd = (size_t)b * D_SZ + d;

        float4 kv = *reinterpret_cast<const float4*>(sC + b_local * SC_STRIDE + d_local * 4);
        kv.x += bias.x; kv.y += bias.y; kv.z += bias.z; kv.w += bias.w;

        float4 c4 = ldg_cs4(cache4 + bd);
        float xv = ldg_cs(x + bd);

        float nc0 = c4.y, nc1 = c4.z, nc2 = c4.w, nc3 = xv;
        float s = nc0 * kv.x + nc1 * kv.y + nc2 * kv.z + nc3 * kv.w;

        stg_cs(out + bd, silu(s));
        stg_cs4(ncache4 + bd, make_float4(nc0, nc1, nc2, nc3));
    }
}

// ---------------------------------------------------------------------------
// launch
// ---------------------------------------------------------------------------
extern "C" void kernel_launch(void* const* d_in, const int* in_sizes, int n_in,
                              void* d_out, int out_size) {
    const float* x     = (const float*)d_in[0];  // (B,1,D)
    const float* gi    = (const float*)d_in[1];  // (B,1,D)
    const float* cache = (const float*)d_in[2];  // (B,D,W)
    const float* w1    = (const float*)d_in[3];  // (D,H)
    const float* w2    = (const float*)d_in[4];  // (H,D*W)
    const float* b2    = (const float*)d_in[5];  // (D*W)

    float* out    = (float*)d_out;               // (B,1,D)
    float* ncache = out + (size_t)B_SZ * D_SZ;   // (B,D,W)

    cudaFuncSetAttribute(dsc_gemm1, cudaFuncAttributeMaxDynamicSharedMemorySize, G1SMEM);
    cudaFuncSetAttribute(dsc_gemm2, cudaFuncAttributeMaxDynamicSharedMemorySize, G2SMEM);

    __half* gt;  cudaGetSymbolAddress((void**)&gt,  g_gt);
    __half* w1t; cudaGetSymbolAddress((void**)&w1t, g_w1t);
    __half* w2t; cudaGetSymbolAddress((void**)&w2t, g_w2t);

    // P1: G permute (coalesced) and w1 transpose run concurrently
    prepass1<<<NG_G + NB_W1T, 256>>>(gi, w1);

    // gemm1 (z=0: full-K compute, direct h) + w2 transpose (z=1) co-scheduled
    dsc_gemm1<<<dim3(32, 8, 2), 256, G1SMEM>>>(gt, w1t, w2);

    dsc_gemm2<<<dim3(32, 256), 256, G2SMEM>>>(x, cache, w2t, b2, out, ncache);
}

// round 17
// speedup vs baseline: 1.0829x; 1.0317x over previous
#include <cuda_runtime.h>
#include <cuda_fp16.h>
#include <cstdint>

#define B_SZ 4096
#define D_SZ 4096
#define W_SZ 4
#define H_SZ 512
#define BKH 32   // halves per k-iteration (64 B rows)

// Static scratch (allocation-free). fp16 GEMM operands stored pair-permuted:
// within each 32-half k-group (16 pairs), pair p (halves 2p,2p+1) is stored at
// pair-position pos16(p) = 4*(p&3) + (p>>2). A thread (tig) then finds pairs
// {tig, tig+4, tig+8, tig+12} contiguous -> one LDS.128 per fragment covering
// BOTH m16n8k16 k-steps of a 32-half chunk.
__device__ __half g_h[B_SZ * H_SZ];            // fp16(silu(G@w1)), [b][h_perm]
__device__ __half g_gt[B_SZ * D_SZ];           // fp16 G, [b][d_perm]
__device__ __half g_w1t[H_SZ * D_SZ];          // fp16 w1^T, [h][d_perm]
__device__ __half g_w2t[D_SZ * W_SZ * H_SZ];   // fp16 w2^T, [n][h_perm]
__device__ float  g_p[2 * B_SZ * H_SZ];        // gemm1 split-K partials (fp32)

// ---------------------------------------------------------------------------
// helpers
// ---------------------------------------------------------------------------
__device__ __forceinline__ void mma_f16(float d[4], const uint32_t a[4], const uint32_t b[2]) {
    asm volatile(
        "mma.sync.aligned.m16n8k16.row.col.f32.f16.f16.f32 "
        "{%0,%1,%2,%3}, {%4,%5,%6,%7}, {%8,%9}, {%0,%1,%2,%3};\n"
        : "+f"(d[0]), "+f"(d[1]), "+f"(d[2]), "+f"(d[3])
        : "r"(a[0]), "r"(a[1]), "r"(a[2]), "r"(a[3]), "r"(b[0]), "r"(b[1]));
}

__device__ __forceinline__ float silu(float v) {
    return v * (1.0f / (1.0f + __expf(-v)));
}

__device__ __forceinline__ uint32_t smem_u32(const void* p) {
    uint32_t a;
    asm("{ .reg .u64 t; cvta.to.shared.u64 t, %1; cvt.u32.u64 %0, t; }" : "=r"(a) : "l"(p));
    return a;
}

__device__ __forceinline__ void cp16u(uint32_t dst_smem, const void* src) {
    asm volatile("cp.async.cg.shared.global [%0], [%1], 16;\n"
                 :: "r"(dst_smem), "l"(src) : "memory");
}
__device__ __forceinline__ void cp_commit() {
    asm volatile("cp.async.commit_group;\n" ::: "memory");
}
template <int N>
__device__ __forceinline__ void cp_wait() {
    asm volatile("cp.async.wait_group %0;\n" :: "n"(N) : "memory");
}

__device__ __forceinline__ uint4 lds128(uint32_t addr) {
    uint4 v;
    asm volatile("ld.shared.v4.b32 {%0,%1,%2,%3}, [%4];"
                 : "=r"(v.x), "=r"(v.y), "=r"(v.z), "=r"(v.w) : "r"(addr));
    return v;
}

// streaming (evict-first) global accessors — keep w2t/h resident in L2
__device__ __forceinline__ float4 ldg_cs4(const float4* p) {
    float4 v;
    asm volatile("ld.global.cs.v4.f32 {%0,%1,%2,%3}, [%4];"
                 : "=f"(v.x), "=f"(v.y), "=f"(v.z), "=f"(v.w) : "l"(p));
    return v;
}
__device__ __forceinline__ float ldg_cs(const float* p) {
    float v;
    asm volatile("ld.global.cs.f32 %0, [%1];" : "=f"(v) : "l"(p));
    return v;
}
__device__ __forceinline__ void stg_cs4(float4* p, float4 v) {
    asm volatile("st.global.cs.v4.f32 [%0], {%1,%2,%3,%4};"
                 :: "l"(p), "f"(v.x), "f"(v.y), "f"(v.z), "f"(v.w));
}
__device__ __forceinline__ void stg_cs(float* p, float v) {
    asm volatile("st.global.cs.f32 [%0], %1;" :: "l"(p), "f"(v));
}

// 32-half tile rows are 64 B; 16 B chunk q stored at q ^ (row & 3).
__device__ __forceinline__ uint32_t frag_addr(uint32_t base, int row, int tig) {
    return base + (uint32_t)row * 64u + (uint32_t)((tig ^ (row & 3)) << 4);
}

__host__ __device__ __forceinline__ int pos16(int p) {
    return ((p & 3) << 2) | (p >> 2);
}

// ---------------------------------------------------------------------------
// Prepass 1 (merged, coalesced): blocks [0, NG_G) do G fp32->fp16 pair-permute
// (one 16B output chunk per thread); blocks [NG_G, +NB_W1T) transpose w1.
// ---------------------------------------------------------------------------
#define NG_G   (B_SZ * D_SZ / 8 / 256)           // 8192 blocks
#define NB_W1T ((H_SZ / 32) * (D_SZ / 32))       // 2048 blocks

__global__ __launch_bounds__(256) void prepass1(const float* __restrict__ gi,
                                                const float* __restrict__ w1) {
    __shared__ float t[32][33];
    int bid = blockIdx.x, tid = threadIdx.x;

    if (bid < NG_G) {
        int tt = bid * 256 + tid;                // chunk id
        int g = tt >> 2, q = tt & 3;             // group, chunk-in-group
        const float2* s = reinterpret_cast<const float2*>(gi) + (size_t)g * 16 + q;
        uint32_t pk[4];
#pragma unroll
        for (int i = 0; i < 4; i++) {            // slot 4q+i <- original pair 4i+q
            float2 v = s[4 * i];
            __half2 h = __floats2half2_rn(v.x, v.y);
            pk[i] = *reinterpret_cast<uint32_t*>(&h);
        }
        reinterpret_cast<uint4*>(g_gt)[tt] = make_uint4(pk[0], pk[1], pk[2], pk[3]);
    } else {
        int idx = bid - NG_G;
        int bx = idx & 15, by = idx >> 4;
        int c0 = bx * 32, r0 = by * 32;
        int tx = tid & 31, ty = tid >> 5;
#pragma unroll
        for (int j = ty; j < 32; j += 8)
            t[j][tx] = w1[(size_t)(r0 + j) * H_SZ + c0 + tx];
        __syncthreads();
        int px = 2 * pos16(tx >> 1) + (tx & 1);
#pragma unroll
        for (int j = ty; j < 32; j += 8)
            g_w1t[(size_t)(c0 + j) * D_SZ + r0 + px] = __float2half_rn(t[tx][j]);
    }
}

// Reduce split-K partials, coalesced: one uint4 output chunk per thread.
// h = fp16(silu(p0+p1)), pair-permuted along h. Partials are L2-resident
// (plain stores in gemm1) so these reads mostly hit L2.
__global__ __launch_bounds__(256) void reduce_silu(int nchunks) {
    int tt = blockIdx.x * blockDim.x + threadIdx.x;
    if (tt >= nchunks) return;
    int g = tt >> 2, q = tt & 3;
    const float2* p0 = reinterpret_cast<const float2*>(g_p) + (size_t)g * 16 + q;
    const float2* p1 = p0 + (size_t)(B_SZ * H_SZ / 2);
    uint32_t pk[4];
#pragma unroll
    for (int i = 0; i < 4; i++) {
        float2 a = p0[4 * i], b = p1[4 * i];
        __half2 h = __floats2half2_rn(silu(a.x + b.x), silu(a.y + b.y));
        pk[i] = *reinterpret_cast<uint32_t*>(&h);
    }
    reinterpret_cast<uint4*>(g_h)[tt] = make_uint4(pk[0], pk[1], pk[2], pk[3]);
}

// ===========================================================================
// Kernel 1: split-K partial of G@w1 (z<2) + w2->w2^T transpose slice (z==2).
// GEMM: BM=128 BN=64, BK=32 halves, S=4 (48 KB), warp grid 4x2, 32x32,
// 3 CTAs/SM. 512 compute CTAs keep nearly all SMs at >=2-CTA residency
// (the proven at-cap point). Partials stored PLAIN -> L2-resident for reduce.
// ===========================================================================
#define S1 4
#define A_STG 8192                        // 128 rows * 64 B
#define B_STG 4096                        // 64 rows * 64 B
#define G1SMEM (S1 * (A_STG + B_STG))     // 49152 B

extern __shared__ float dynsmem[];

__global__ __launch_bounds__(256, 3) void dsc_gemm1(const __half* __restrict__ G,
                                                    const __half* __restrict__ w1t,
                                                    const float* __restrict__ w2) {
    int tid = threadIdx.x;

    if (blockIdx.z == 2) {
        // --- w2 [H][D*W] -> w2t [D*W][H], permute along H. 256 blocks x 32 tiles.
        float* t = dynsmem;                              // [32][33]
        int tx = tid & 31, ty = tid >> 5;
        int bid = blockIdx.y * 32 + blockIdx.x;          // 0..255
        int px = 2 * pos16(tx >> 1) + (tx & 1);
#pragma unroll 1
        for (int tt = 0; tt < 32; tt++) {
            int tile = bid * 32 + tt;
            int cx = tile & 511, cy = tile >> 9;
            int c0 = cx * 32, r0 = cy * 32;
#pragma unroll
            for (int j = ty; j < 32; j += 8)
                t[j * 33 + tx] = w2[(size_t)(r0 + j) * (D_SZ * W_SZ) + c0 + tx];
            __syncthreads();
#pragma unroll
            for (int j = ty; j < 32; j += 8)
                g_w2t[(size_t)(c0 + j) * H_SZ + r0 + px] = __float2half_rn(t[tx * 33 + j]);
            __syncthreads();
        }
        return;
    }

    uint32_t sb = smem_u32(dynsmem);
    uint32_t aS = sb, bS = sb + S1 * A_STG;

    int lane = tid & 31, warp = tid >> 5;
    int warpM = warp >> 1, warpN = warp & 1;
    int g = lane >> 2, tig = lane & 3;
    int bm = blockIdx.x, bn = blockIdx.y, sk = blockIdx.z;

    const __half* A = G + (size_t)bm * 128 * D_SZ + sk * 2048;
    const __half* B = w1t + (size_t)bn * 64 * D_SZ + sk * 2048;

    auto load_stage = [&](int j) {
        uint32_t a_s = aS + (j & (S1 - 1)) * A_STG;
        uint32_t b_s = bS + (j & (S1 - 1)) * B_STG;
#pragma unroll
        for (int t = 0; t < 2; t++) {
            int id = tid + 256 * t;
            int r = id >> 2, q = id & 3;
            cp16u(a_s + r * 64 + ((q ^ (r & 3)) << 4), A + (size_t)r * D_SZ + j * BKH + q * 8);
        }
        {
            int r = tid >> 2, q = tid & 3;
            cp16u(b_s + r * 64 + ((q ^ (r & 3)) << 4), B + (size_t)r * D_SZ + j * BKH + q * 8);
        }
    };

    const int nIter = 2048 / BKH;  // 64
#pragma unroll
    for (int s = 0; s < S1 - 1; s++) { load_stage(s); cp_commit(); }

    float acc[2][4][4] = {};
    for (int it = 0; it < nIter; it++) {
        cp_wait<S1 - 2>();
        __syncthreads();
        int nxt = it + S1 - 1;
        if (nxt < nIter) load_stage(nxt);
        cp_commit();
        uint32_t a_s = aS + (it & (S1 - 1)) * A_STG;
        uint32_t b_s = bS + (it & (S1 - 1)) * B_STG;

        uint4 bb[4], alo[2], ahi[2];
#pragma unroll
        for (int nt = 0; nt < 4; nt++)
            bb[nt] = lds128(frag_addr(b_s, warpN * 32 + nt * 8 + g, tig));
#pragma unroll
        for (int mt = 0; mt < 2; mt++) {
            int r = warpM * 32 + mt * 16 + g;
            alo[mt] = lds128(frag_addr(a_s, r, tig));
            ahi[mt] = lds128(frag_addr(a_s, r + 8, tig));
        }
#pragma unroll
        for (int ks = 0; ks < 2; ks++) {
#pragma unroll
            for (int mt = 0; mt < 2; mt++) {
                uint32_t a[4];
                if (ks == 0) { a[0] = alo[mt].x; a[1] = ahi[mt].x; a[2] = alo[mt].y; a[3] = ahi[mt].y; }
                else         { a[0] = alo[mt].z; a[1] = ahi[mt].z; a[2] = alo[mt].w; a[3] = ahi[mt].w; }
#pragma unroll
                for (int nt = 0; nt < 4; nt++) {
                    uint32_t b[2];
                    if (ks == 0) { b[0] = bb[nt].x; b[1] = bb[nt].y; }
                    else         { b[0] = bb[nt].z; b[1] = bb[nt].w; }
                    mma_f16(acc[mt][nt], a, b);
                }
            }
        }
    }

    // raw fp32 partial store — PLAIN stores so partials stay L2-resident
    float* P = g_p + (size_t)sk * B_SZ * H_SZ;
#pragma unroll
    for (int mt = 0; mt < 2; mt++) {
#pragma unroll
        for (int nt = 0; nt < 4; nt++) {
            int row = bm * 128 + warpM * 32 + mt * 16 + g;
            int col = bn * 64 + warpN * 32 + nt * 8 + 2 * tig;
            *reinterpret_cast<float2*>(P + (size_t)row * H_SZ + col) =
                make_float2(acc[mt][nt][0], acc[mt][nt][1]);
            *reinterpret_cast<float2*>(P + (size_t)(row + 8) * H_SZ + col) =
                make_float2(acc[mt][nt][2], acc[mt][nt][3]);
        }
    }
}

// ===========================================================================
// Kernel 2 (unchanged, at the HMMA cap): kernels = h@w2^T + b2, fused conv.
// M=4096 N=16384 K=512. BM=128 BN=64, warp grid 4x2, 32x32,
// S=5 stages (60 KB), 3 CTAs/SM, streaming epilogue.
// ===========================================================================
#define S2 5
#define G2SMEM (S2 * (A_STG + B_STG))     // 61440 B
#define SC_STRIDE 68

__global__ __launch_bounds__(256, 3) void dsc_gemm2(const float* __restrict__ x,
                                                    const float* __restrict__ cache,
                                                    const __half* __restrict__ w2t,
                                                    const float* __restrict__ b2,
                                                    float* __restrict__ out,
                                                    float* __restrict__ new_cache) {
    uint32_t sb = smem_u32(dynsmem);
    uint32_t aS = sb, bS = sb + S2 * A_STG;

    int tid = threadIdx.x, lane = tid & 31, warp = tid >> 5;
    int warpM = warp >> 1, warpN = warp & 1;
    int g = lane >> 2, tig = lane & 3;
    int bm = blockIdx.x, bn = blockIdx.y;

    const __half* A = g_h + (size_t)bm * 128 * H_SZ;
    const __half* B = w2t + (size_t)bn * 64 * H_SZ;

    auto load_stage = [&](int j) {
        uint32_t a_s = aS + (j % S2) * A_STG;
        uint32_t b_s = bS + (j % S2) * B_STG;
#pragma unroll
        for (int t = 0; t < 2; t++) {
            int id = tid + 256 * t;
            int r = id >> 2, q = id & 3;
            cp16u(a_s + r * 64 + ((q ^ (r & 3)) << 4), A + (size_t)r * H_SZ + j * BKH + q * 8);
        }
        {
            int r = tid >> 2, q = tid & 3;
            cp16u(b_s + r * 64 + ((q ^ (r & 3)) << 4), B + (size_t)r * H_SZ + j * BKH + q * 8);
        }
    };

    const int nIter = H_SZ / BKH;  // 16
#pragma unroll
    for (int s = 0; s < S2 - 1; s++) { load_stage(s); cp_commit(); }

    float acc[2][4][4] = {};
    for (int it = 0; it < nIter; it++) {
        cp_wait<S2 - 2>();
        __syncthreads();
        int nxt = it + S2 - 1;
        if (nxt < nIter) load_stage(nxt);
        cp_commit();
        uint32_t a_s = aS + (it % S2) * A_STG;
        uint32_t b_s = bS + (it % S2) * B_STG;

        uint4 bb[4], alo[2], ahi[2];
#pragma unroll
        for (int nt = 0; nt < 4; nt++)
            bb[nt] = lds128(frag_addr(b_s, warpN * 32 + nt * 8 + g, tig));
#pragma unroll
        for (int mt = 0; mt < 2; mt++) {
            int r = warpM * 32 + mt * 16 + g;
            alo[mt] = lds128(frag_addr(a_s, r, tig));
            ahi[mt] = lds128(frag_addr(a_s, r + 8, tig));
        }
#pragma unroll
        for (int ks = 0; ks < 2; ks++) {
#pragma unroll
            for (int mt = 0; mt < 2; mt++) {
                uint32_t a[4];
                if (ks == 0) { a[0] = alo[mt].x; a[1] = ahi[mt].x; a[2] = alo[mt].y; a[3] = ahi[mt].y; }
                else         { a[0] = alo[mt].z; a[1] = ahi[mt].z; a[2] = alo[mt].w; a[3] = ahi[mt].w; }
#pragma unroll
                for (int nt = 0; nt < 4; nt++) {
                    uint32_t b[2];
                    if (ks == 0) { b[0] = bb[nt].x; b[1] = bb[nt].y; }
                    else         { b[0] = bb[nt].z; b[1] = bb[nt].w; }
                    mma_f16(acc[mt][nt], a, b);
                }
            }
        }
    }

    __syncthreads();  // mainloop smem reads done; reuse as C tile

    // Single-pass epilogue: all 8 warps dump their 32x32 quadrant, then conv.
    float* sC = dynsmem;
#pragma unroll
    for (int mt = 0; mt < 2; mt++) {
#pragma unroll
        for (int nt = 0; nt < 4; nt++) {
            int r = warpM * 32 + mt * 16 + g;
            int c = warpN * 32 + nt * 8 + 2 * tig;
            sC[r * SC_STRIDE + c] = acc[mt][nt][0];
            sC[r * SC_STRIDE + c + 1] = acc[mt][nt][1];
            sC[(r + 8) * SC_STRIDE + c] = acc[mt][nt][2];
            sC[(r + 8) * SC_STRIDE + c + 1] = acc[mt][nt][3];
        }
    }
    __syncthreads();

    const float4* cache4 = reinterpret_cast<const float4*>(cache);
    float4* ncache4 = reinterpret_cast<float4*>(new_cache);
    const float4* b2_4 = reinterpret_cast<const float4*>(b2);

    int d_local = tid & 15;
    int d = bn * 16 + d_local;
    float4 bias = b2_4[d];
#pragma unroll
    for (int i = 0; i < 8; i++) {
        int b_local = (tid >> 4) + i * 16;
        int b = bm * 128 + b_local;
        size_t bd = (size_t)b * D_SZ + d;

        float4 kv = *reinterpret_cast<const float4*>(sC + b_local * SC_STRIDE + d_local * 4);
        kv.x += bias.x; kv.y += bias.y; kv.z += bias.z; kv.w += bias.w;

        float4 c4 = ldg_cs4(cache4 + bd);
        float xv = ldg_cs(x + bd);

        float nc0 = c4.y, nc1 = c4.z, nc2 = c4.w, nc3 = xv;
        float s = nc0 * kv.x + nc1 * kv.y + nc2 * kv.z + nc3 * kv.w;

        stg_cs(out + bd, silu(s));
        stg_cs4(ncache4 + bd, make_float4(nc0, nc1, nc2, nc3));
    }
}

// ---------------------------------------------------------------------------
// launch
// ---------------------------------------------------------------------------
extern "C" void kernel_launch(void* const* d_in, const int* in_sizes, int n_in,
                              void* d_out, int out_size) {
    const float* x     = (const float*)d_in[0];  // (B,1,D)
    const float* gi    = (const float*)d_in[1];  // (B,1,D)
    const float* cache = (const float*)d_in[2];  // (B,D,W)
    const float* w1    = (const float*)d_in[3];  // (D,H)
    const float* w2    = (const float*)d_in[4];  // (H,D*W)
    const float* b2    = (const float*)d_in[5];  // (D*W)

    float* out    = (float*)d_out;               // (B,1,D)
    float* ncache = out + (size_t)B_SZ * D_SZ;   // (B,D,W)

    cudaFuncSetAttribute(dsc_gemm1, cudaFuncAttributeMaxDynamicSharedMemorySize, G1SMEM);
    cudaFuncSetAttribute(dsc_gemm2, cudaFuncAttributeMaxDynamicSharedMemorySize, G2SMEM);

    __half* gt;  cudaGetSymbolAddress((void**)&gt,  g_gt);
    __half* w1t; cudaGetSymbolAddress((void**)&w1t, g_w1t);
    __half* w2t; cudaGetSymbolAddress((void**)&w2t, g_w2t);

    // P1: G permute (coalesced) and w1 transpose run concurrently
    prepass1<<<NG_G + NB_W1T, 256>>>(gi, w1);

    // gemm1 (z<2: split-K compute) + w2 transpose (z==2) co-scheduled
    dsc_gemm1<<<dim3(32, 8, 3), 256, G1SMEM>>>(gt, w1t, w2);

    // reduce: one 16B chunk per thread (coalesced, partials hit L2)
    int nchunks = B_SZ * H_SZ / 8;
    reduce_silu<<<(nchunks + 255) / 256, 256>>>(nchunks);

    dsc_gemm2<<<dim3(32, 256), 256, G2SMEM>>>(x, cache, w2t, b2, out, ncache);
}